// round 10
// baseline (speedup 1.0000x reference)
#include <cuda_runtime.h>
#include <cstdint>

// Problem constants
#define BB 4
#define TT 1024
#define DD 1024
#define HH 16
#define DH 64
#define BT (BB*TT)   // 4096

// Scratch (allocation-free: __device__ globals)
__device__ float g_Q[BT*DD];                    // 16 MB
__device__ float g_K[BT*DD];                    // 16 MB
__device__ float g_V[BT*DD];                    // 16 MB
__device__ float g_A[(size_t)BB*HH*TT*TT];      // 256 MB attn matrix
__device__ float g_Xhi[BT*DD];
__device__ float g_Xlo[BT*DD];
__device__ float g_Wthi[3][DD*DD];
__device__ float g_Wtlo[3][DD*DD];
__device__ float g_mx[BB*HH*TT];                // per-row max
__device__ float g_invs[BB*HH*TT];              // per-row 1/sum(exp)

// ---------------------------------------------------------------------------
// Helpers
// ---------------------------------------------------------------------------
__device__ __forceinline__ uint32_t smem_u32(const void* p) {
    uint32_t a;
    asm("{ .reg .u64 t; cvta.to.shared.u64 t, %1; cvt.u32.u64 %0, t; }" : "=r"(a) : "l"(p));
    return a;
}
__device__ __forceinline__ float to_tf32(float v) {
    uint32_t u;
    asm("cvt.rna.tf32.f32 %0, %1;" : "=r"(u) : "f"(v));
    return __uint_as_float(u);
}
__device__ __forceinline__ void cp16(uint32_t dst, const void* src) {
    asm volatile("cp.async.cg.shared.global [%0], [%1], 16;" :: "r"(dst), "l"(src));
}
#define CP_COMMIT() asm volatile("cp.async.commit_group;" ::: "memory")
#define CP_WAIT1()  asm volatile("cp.async.wait_group 1;" ::: "memory")
#define CP_WAIT0()  asm volatile("cp.async.wait_group 0;" ::: "memory")

#define MMA_TF32(d, a, b) \
    asm volatile("mma.sync.aligned.m16n8k8.row.col.f32.tf32.tf32.f32 " \
        "{%0,%1,%2,%3}, {%4,%5,%6,%7}, {%8,%9}, {%0,%1,%2,%3};" \
        : "+f"((d)[0]), "+f"((d)[1]), "+f"((d)[2]), "+f"((d)[3]) \
        : "r"((a)[0]), "r"((a)[1]), "r"((a)[2]), "r"((a)[3]), \
          "r"((b)[0]), "r"((b)[1]))

// ---------------------------------------------------------------------------
// Prep 1: split X into tf32 hi/lo
// ---------------------------------------------------------------------------
__global__ __launch_bounds__(256) void split_x_kernel(const float* __restrict__ x)
{
    const size_t i4 = ((size_t)blockIdx.x * 256 + threadIdx.x) * 4;
    float4 v = *reinterpret_cast<const float4*>(&x[i4]);
    float4 h, l;
    h.x = to_tf32(v.x); l.x = to_tf32(v.x - h.x);
    h.y = to_tf32(v.y); l.y = to_tf32(v.y - h.y);
    h.z = to_tf32(v.z); l.z = to_tf32(v.z - h.z);
    h.w = to_tf32(v.w); l.w = to_tf32(v.w - h.w);
    *reinterpret_cast<float4*>(&g_Xhi[i4]) = h;
    *reinterpret_cast<float4*>(&g_Xlo[i4]) = l;
}

// ---------------------------------------------------------------------------
// Prep 2: transpose W + tf32 hi/lo split: Wt[n][k] = W[k][n]
// ---------------------------------------------------------------------------
__global__ void wtrans_kernel(const float* __restrict__ W, int widx)
{
    __shared__ float s[32][33];
    const int tx = threadIdx.x;
    const int ty = threadIdx.y;
    const int k0 = blockIdx.x * 32;
    const int n0 = blockIdx.y * 32;

    #pragma unroll
    for (int i = 0; i < 4; i++)
        s[ty + i * 8][tx] = W[(size_t)(k0 + ty + i * 8) * DD + n0 + tx];
    __syncthreads();

    float* hi = g_Wthi[widx];
    float* lo = g_Wtlo[widx];
    #pragma unroll
    for (int i = 0; i < 4; i++) {
        float v = s[tx][ty + i * 8];
        float h = to_tf32(v);
        hi[(size_t)(n0 + ty + i * 8) * DD + k0 + tx] = h;
        lo[(size_t)(n0 + ty + i * 8) * DD + k0 + tx] = to_tf32(v - h);
    }
}

// ---------------------------------------------------------------------------
// Kernel 1: projection GEMM via mma.sync m16n8k8 tf32, 3xTF32 hi/lo split.
// ---------------------------------------------------------------------------
#define ROWPAD 36
#define A_F    (128 * ROWPAD)
#define B_F    (128 * 32)
#define STG_F  (2 * A_F + 2 * B_F)
#define PROJ_SMEM (2 * STG_F * 4)
#define NCHUNK 32

__global__ __launch_bounds__(256, 1) void proj_mma_kernel(
    const float* __restrict__ Ahi_g, const float* __restrict__ Alo_g,
    const float* __restrict__ Bhi_g, const float* __restrict__ Blo_g,
    const float* __restrict__ bias, float* __restrict__ C)
{
    extern __shared__ float sm[];
    const uint32_t sbase = smem_u32(sm);

    const int tid = threadIdx.x;
    const int wid = tid >> 5;
    const int lane = tid & 31;
    const int lq  = lane >> 2;
    const int lr  = lane & 3;

    const int row0 = blockIdx.y * 128;
    const int col0 = blockIdx.x * 128;

    const int m0 = (wid >> 1) * 32;
    const int n0 = (wid & 1) * 64;

    auto load_chunk = [&](int kc, int stage) {
        const int k0 = kc * 32;
        const uint32_t st = sbase + (uint32_t)stage * STG_F * 4;
        #pragma unroll
        for (int i = 0; i < 4; i++) {
            const int c = tid + i * 256;
            const int r = c >> 3;
            const int o = c & 7;
            const uint32_t soA = (uint32_t)(r * ROWPAD * 4 + o * 16);
            const uint32_t soB = (uint32_t)(r * 128 + ((o ^ (r & 7)) * 16));
            const size_t ga = (size_t)(row0 + r) * DD + k0 + o * 4;
            const size_t gb = (size_t)(col0 + r) * DD + k0 + o * 4;
            cp16(st + 0 * A_F * 4 + soA, &Ahi_g[ga]);
            cp16(st + 1 * A_F * 4 + soA, &Alo_g[ga]);
            cp16(st + (2 * A_F + 0 * B_F) * 4 + soB, &Bhi_g[gb]);
            cp16(st + (2 * A_F + 1 * B_F) * 4 + soB, &Blo_g[gb]);
        }
        CP_COMMIT();
    };

    float acc[2][8][4];
    #pragma unroll
    for (int mt = 0; mt < 2; mt++)
        #pragma unroll
        for (int nt = 0; nt < 8; nt++)
            #pragma unroll
            for (int r = 0; r < 4; r++)
                acc[mt][nt][r] = 0.f;

    load_chunk(0, 0);
    load_chunk(1, 1);

    for (int kc = 0; kc < NCHUNK; kc++) {
        if (kc == NCHUNK - 1) { CP_WAIT0(); } else { CP_WAIT1(); }
        __syncthreads();

        const float* st = sm + (kc & 1) * STG_F;
        const float* Ah = st;
        const float* Al = st + A_F;
        const float* Bh = st + 2 * A_F;
        const float* Bl = st + 2 * A_F + B_F;

        #pragma unroll
        for (int s = 0; s < 4; s++) {
            const int k = s * 8;
            uint32_t ahi[2][4], alo[2][4];
            #pragma unroll
            for (int mt = 0; mt < 2; mt++) {
                const int r = m0 + mt * 16 + lq;
                ahi[mt][0] = __float_as_uint(Ah[r * ROWPAD + k + lr]);
                ahi[mt][1] = __float_as_uint(Ah[(r + 8) * ROWPAD + k + lr]);
                ahi[mt][2] = __float_as_uint(Ah[r * ROWPAD + k + 4 + lr]);
                ahi[mt][3] = __float_as_uint(Ah[(r + 8) * ROWPAD + k + 4 + lr]);
                alo[mt][0] = __float_as_uint(Al[r * ROWPAD + k + lr]);
                alo[mt][1] = __float_as_uint(Al[(r + 8) * ROWPAD + k + lr]);
                alo[mt][2] = __float_as_uint(Al[r * ROWPAD + k + 4 + lr]);
                alo[mt][3] = __float_as_uint(Al[(r + 8) * ROWPAD + k + 4 + lr]);
            }
            #pragma unroll
            for (int nt = 0; nt < 8; nt++) {
                const int n = n0 + nt * 8 + lq;
                const int nb = n * 32;
                const int x0 = ((2 * s) ^ (n & 7)) << 2;
                const int x1 = ((2 * s + 1) ^ (n & 7)) << 2;
                uint32_t bhi[2], blo[2];
                bhi[0] = __float_as_uint(Bh[nb + x0 + lr]);
                bhi[1] = __float_as_uint(Bh[nb + x1 + lr]);
                blo[0] = __float_as_uint(Bl[nb + x0 + lr]);
                blo[1] = __float_as_uint(Bl[nb + x1 + lr]);
                MMA_TF32(acc[0][nt], ahi[0], bhi);
                MMA_TF32(acc[1][nt], ahi[1], bhi);
                MMA_TF32(acc[0][nt], ahi[0], blo);
                MMA_TF32(acc[1][nt], ahi[1], blo);
                MMA_TF32(acc[0][nt], alo[0], bhi);
                MMA_TF32(acc[1][nt], alo[1], bhi);
            }
        }
        __syncthreads();
        if (kc + 2 < NCHUNK) load_chunk(kc + 2, kc & 1);
    }

    #pragma unroll
    for (int mt = 0; mt < 2; mt++) {
        const int rm = row0 + m0 + mt * 16 + lq;
        #pragma unroll
        for (int nt = 0; nt < 8; nt++) {
            const int cn = col0 + n0 + nt * 8 + 2 * lr;
            const float2 bv = *reinterpret_cast<const float2*>(&bias[cn]);
            float2 v0 = make_float2(acc[mt][nt][0] + bv.x, acc[mt][nt][1] + bv.y);
            float2 v1 = make_float2(acc[mt][nt][2] + bv.x, acc[mt][nt][3] + bv.y);
            *reinterpret_cast<float2*>(&C[(size_t)rm * DD + cn])       = v0;
            *reinterpret_cast<float2*>(&C[(size_t)(rm + 8) * DD + cn]) = v1;
        }
    }
}

// ---------------------------------------------------------------------------
// Kernel 2: attn via mma.sync tf32 3x.
// attn[t][s] = temp * sum_d K[d][t] * V[d][s].
// A = K^T [128 t][64 d], B = V^T [128 s][64 d], staged transposed with
// on-the-fly hi/lo split, pad-33.  2 d-chunks of 32.
// 8 warps (4x2), warp tile 32x64.
// ---------------------------------------------------------------------------
#define ATS_F 4224   // 128*33
#define ATTN_SMEM (4 * ATS_F * 4)   // 67584 bytes

__global__ __launch_bounds__(256, 1) void attn_mma_kernel(const float* __restrict__ temperature)
{
    extern __shared__ float sma[];
    float* Ash = sma;                 // K^T hi [t][d] pad 33
    float* Asl = sma + ATS_F;
    float* Bsh = sma + 2 * ATS_F;     // V^T hi [s][d] pad 33
    float* Bsl = sma + 3 * ATS_F;

    const int tid = threadIdx.x;
    const int wid = tid >> 5;
    const int lane = tid & 31;
    const int lq = lane >> 2, lr = lane & 3;
    const int bh = blockIdx.z, b = bh >> 4, h = bh & 15;
    const int t0 = blockIdx.y * 128;
    const int s0 = blockIdx.x * 128;
    const int m0 = (wid >> 1) * 32;   // 0,32,64,96 over t
    const int n0 = (wid & 1) * 64;    // 0,64 over s

    const size_t base = (size_t)b * TT * DD + (size_t)(h * DH) * DD;
    const float* Kh = g_K + base;
    const float* Vh = g_V + base;

    float acc[2][8][4];
    #pragma unroll
    for (int mt = 0; mt < 2; mt++)
        #pragma unroll
        for (int nt = 0; nt < 8; nt++)
            #pragma unroll
            for (int r = 0; r < 4; r++)
                acc[mt][nt][r] = 0.f;

    for (int dc = 0; dc < 2; dc++) {
        const int d0 = dc * 32;
        if (dc) __syncthreads();
        // stage K^T and V^T, hi/lo split, transposed scalar stores
        #pragma unroll
        for (int i = 0; i < 4; i++) {
            const int f = i * 256 + tid;       // 0..1023
            const int dd = f >> 5;             // 0..31
            const int c4 = (f & 31) * 4;       // 0..124
            float4 kv = *reinterpret_cast<const float4*>(&Kh[(size_t)(d0 + dd) * DD + t0 + c4]);
            float4 vv = *reinterpret_cast<const float4*>(&Vh[(size_t)(d0 + dd) * DD + s0 + c4]);
            float kh0 = to_tf32(kv.x), kh1 = to_tf32(kv.y), kh2 = to_tf32(kv.z), kh3 = to_tf32(kv.w);
            Ash[(c4 + 0) * 33 + dd] = kh0;
            Ash[(c4 + 1) * 33 + dd] = kh1;
            Ash[(c4 + 2) * 33 + dd] = kh2;
            Ash[(c4 + 3) * 33 + dd] = kh3;
            Asl[(c4 + 0) * 33 + dd] = to_tf32(kv.x - kh0);
            Asl[(c4 + 1) * 33 + dd] = to_tf32(kv.y - kh1);
            Asl[(c4 + 2) * 33 + dd] = to_tf32(kv.z - kh2);
            Asl[(c4 + 3) * 33 + dd] = to_tf32(kv.w - kh3);
            float vh0 = to_tf32(vv.x), vh1 = to_tf32(vv.y), vh2 = to_tf32(vv.z), vh3 = to_tf32(vv.w);
            Bsh[(c4 + 0) * 33 + dd] = vh0;
            Bsh[(c4 + 1) * 33 + dd] = vh1;
            Bsh[(c4 + 2) * 33 + dd] = vh2;
            Bsh[(c4 + 3) * 33 + dd] = vh3;
            Bsl[(c4 + 0) * 33 + dd] = to_tf32(vv.x - vh0);
            Bsl[(c4 + 1) * 33 + dd] = to_tf32(vv.y - vh1);
            Bsl[(c4 + 2) * 33 + dd] = to_tf32(vv.z - vh2);
            Bsl[(c4 + 3) * 33 + dd] = to_tf32(vv.w - vh3);
        }
        __syncthreads();

        #pragma unroll
        for (int s = 0; s < 4; s++) {
            const int k = s * 8;
            uint32_t ahi[2][4], alo[2][4];
            #pragma unroll
            for (int mt = 0; mt < 2; mt++) {
                const int r = m0 + mt * 16 + lq;
                ahi[mt][0] = __float_as_uint(Ash[r * 33 + k + lr]);
                ahi[mt][1] = __float_as_uint(Ash[(r + 8) * 33 + k + lr]);
                ahi[mt][2] = __float_as_uint(Ash[r * 33 + k + 4 + lr]);
                ahi[mt][3] = __float_as_uint(Ash[(r + 8) * 33 + k + 4 + lr]);
                alo[mt][0] = __float_as_uint(Asl[r * 33 + k + lr]);
                alo[mt][1] = __float_as_uint(Asl[(r + 8) * 33 + k + lr]);
                alo[mt][2] = __float_as_uint(Asl[r * 33 + k + 4 + lr]);
                alo[mt][3] = __float_as_uint(Asl[(r + 8) * 33 + k + 4 + lr]);
            }
            #pragma unroll
            for (int nt = 0; nt < 8; nt++) {
                const int n = n0 + nt * 8 + lq;
                uint32_t bhf[2], blf[2];
                bhf[0] = __float_as_uint(Bsh[n * 33 + k + lr]);
                bhf[1] = __float_as_uint(Bsh[n * 33 + k + 4 + lr]);
                blf[0] = __float_as_uint(Bsl[n * 33 + k + lr]);
                blf[1] = __float_as_uint(Bsl[n * 33 + k + 4 + lr]);
                MMA_TF32(acc[0][nt], ahi[0], bhf);
                MMA_TF32(acc[1][nt], ahi[1], bhf);
                MMA_TF32(acc[0][nt], ahi[0], blf);
                MMA_TF32(acc[1][nt], ahi[1], blf);
                MMA_TF32(acc[0][nt], alo[0], bhf);
                MMA_TF32(acc[1][nt], alo[1], bhf);
            }
        }
    }

    const float tmp = temperature[h];
    float* Abase = g_A + ((size_t)bh * TT + t0) * TT + s0;
    #pragma unroll
    for (int mt = 0; mt < 2; mt++) {
        const int rm = m0 + mt * 16 + lq;
        #pragma unroll
        for (int nt = 0; nt < 8; nt++) {
            const int cn = n0 + nt * 8 + 2 * lr;
            *reinterpret_cast<float2*>(&Abase[(size_t)rm * TT + cn]) =
                make_float2(acc[mt][nt][0] * tmp, acc[mt][nt][1] * tmp);
            *reinterpret_cast<float2*>(&Abase[(size_t)(rm + 8) * TT + cn]) =
                make_float2(acc[mt][nt][2] * tmp, acc[mt][nt][3] * tmp);
        }
    }
}

// ---------------------------------------------------------------------------
// Kernel 3: per-row max + 1/sum(exp) stats (read-only over g_A).
// ---------------------------------------------------------------------------
__global__ __launch_bounds__(256) void rowstat_kernel()
{
    const int warp_in_block = threadIdx.x >> 5;
    const int lane = threadIdx.x & 31;
    const size_t row = (size_t)blockIdx.x * 8 + warp_in_block;

    const float* rp = g_A + row * TT;

    float vals[32];
    float mx = -3.402823466e+38f;
    #pragma unroll
    for (int i = 0; i < 8; i++) {
        float4 v = *reinterpret_cast<const float4*>(&rp[(i * 32 + lane) * 4]);
        vals[i * 4 + 0] = v.x; vals[i * 4 + 1] = v.y;
        vals[i * 4 + 2] = v.z; vals[i * 4 + 3] = v.w;
        mx = fmaxf(mx, fmaxf(fmaxf(v.x, v.y), fmaxf(v.z, v.w)));
    }
    #pragma unroll
    for (int off = 16; off > 0; off >>= 1)
        mx = fmaxf(mx, __shfl_xor_sync(0xffffffffu, mx, off));

    float sum = 0.f;
    #pragma unroll
    for (int i = 0; i < 32; i++)
        sum += __expf(vals[i] - mx);
    #pragma unroll
    for (int off = 16; off > 0; off >>= 1)
        sum += __shfl_xor_sync(0xffffffffu, sum, off);

    if (lane == 0) {
        g_mx[row]   = mx;
        g_invs[row] = 1.0f / sum;
    }
}

// ---------------------------------------------------------------------------
// Kernel 4: out rows = (Qh * invs) @ exp(A - mx) via mma.sync tf32 3x.
// ---------------------------------------------------------------------------
#define QS_F 2304            // 64*36
#define PS_F 4224            // 128*33
#define OUT_SMEM ((2*QS_F + 2*PS_F) * 4)   // 52224 bytes

__global__ __launch_bounds__(256, 1) void out_mma_kernel(float* __restrict__ out)
{
    extern __shared__ float sm2[];
    float* Qh_s = sm2;                 // [64][36] hi
    float* Ql_s = sm2 + QS_F;          // [64][36] lo
    float* Ph_s = sm2 + 2 * QS_F;      // [128 s][33 t] hi
    float* Pl_s = sm2 + 2 * QS_F + PS_F;

    const int tid = threadIdx.x;
    const int wid = tid >> 5;
    const int lane = tid & 31;
    const int lq = lane >> 2, lr = lane & 3;
    const int bh = blockIdx.z, b = bh >> 4, h = bh & 15;
    const int s0 = blockIdx.x * 128;
    const int m0 = (wid >> 2) * 32;    // 0 or 32
    const int n0 = (wid & 3) * 32;     // 0,32,64,96

    const size_t base = (size_t)b * TT * DD + (size_t)(h * DH) * DD;
    const float* Qg   = g_Q + base;
    const float* Ag   = g_A + (size_t)bh * TT * TT;
    const float* mxp  = g_mx + (size_t)bh * TT;
    const float* invp = g_invs + (size_t)bh * TT;

    const int qr0 = tid >> 3;            // 0..31
    const int qo  = (tid & 7) * 4;       // 0..28

    float acc[2][4][4];
    #pragma unroll
    for (int mt = 0; mt < 2; mt++)
        #pragma unroll
        for (int nt = 0; nt < 4; nt++)
            #pragma unroll
            for (int r = 0; r < 4; r++)
                acc[mt][nt][r] = 0.f;

    float4 qv[2], av[4], iv4;
    float mval[4];

    auto ldg_chunk = [&](int kc) {
        const int k0 = kc * 32;
        iv4 = *reinterpret_cast<const float4*>(&invp[k0 + qo]);
        #pragma unroll
        for (int i = 0; i < 2; i++) {
            const int qr = qr0 + i * 32;
            qv[i] = *reinterpret_cast<const float4*>(&Qg[(size_t)qr * DD + k0 + qo]);
        }
        #pragma unroll
        for (int i = 0; i < 4; i++) {
            const int f = i * 256 + tid;
            const int ar = f >> 5;
            const int ac4 = (f & 31) * 4;
            av[i] = *reinterpret_cast<const float4*>(&Ag[(size_t)(k0 + ar) * TT + s0 + ac4]);
            mval[i] = mxp[k0 + ar];
        }
    };

    ldg_chunk(0);
    for (int kc = 0; kc < 32; kc++) {
        if (kc) __syncthreads();
        #pragma unroll
        for (int i = 0; i < 2; i++) {
            const int qr = qr0 + i * 32;
            float v0 = qv[i].x * iv4.x, v1 = qv[i].y * iv4.y;
            float v2 = qv[i].z * iv4.z, v3 = qv[i].w * iv4.w;
            float h0 = to_tf32(v0), h1 = to_tf32(v1), h2 = to_tf32(v2), h3 = to_tf32(v3);
            *reinterpret_cast<float4*>(&Qh_s[qr * 36 + qo]) = make_float4(h0, h1, h2, h3);
            *reinterpret_cast<float4*>(&Ql_s[qr * 36 + qo]) =
                make_float4(to_tf32(v0 - h0), to_tf32(v1 - h1), to_tf32(v2 - h2), to_tf32(v3 - h3));
        }
        #pragma unroll
        for (int i = 0; i < 4; i++) {
            const int f = i * 256 + tid;
            const int ar = f >> 5;
            const int ac4 = (f & 31) * 4;
            const float m = mval[i];
            float e0 = __expf(av[i].x - m), e1 = __expf(av[i].y - m);
            float e2 = __expf(av[i].z - m), e3 = __expf(av[i].w - m);
            float h0 = to_tf32(e0), h1 = to_tf32(e1), h2 = to_tf32(e2), h3 = to_tf32(e3);
            Ph_s[(ac4 + 0) * 33 + ar] = h0;
            Ph_s[(ac4 + 1) * 33 + ar] = h1;
            Ph_s[(ac4 + 2) * 33 + ar] = h2;
            Ph_s[(ac4 + 3) * 33 + ar] = h3;
            Pl_s[(ac4 + 0) * 33 + ar] = to_tf32(e0 - h0);
            Pl_s[(ac4 + 1) * 33 + ar] = to_tf32(e1 - h1);
            Pl_s[(ac4 + 2) * 33 + ar] = to_tf32(e2 - h2);
            Pl_s[(ac4 + 3) * 33 + ar] = to_tf32(e3 - h3);
        }
        __syncthreads();
        if (kc + 1 < 32) ldg_chunk(kc + 1);

        #pragma unroll
        for (int s = 0; s < 4; s++) {
            const int k = s * 8;
            uint32_t ah[2][4], al[2][4];
            #pragma unroll
            for (int mt = 0; mt < 2; mt++) {
                const int r = m0 + mt * 16 + lq;
                ah[mt][0] = __float_as_uint(Qh_s[r * 36 + k + lr]);
                ah[mt][1] = __float_as_uint(Qh_s[(r + 8) * 36 + k + lr]);
                ah[mt][2] = __float_as_uint(Qh_s[r * 36 + k + 4 + lr]);
                ah[mt][3] = __float_as_uint(Qh_s[(r + 8) * 36 + k + 4 + lr]);
                al[mt][0] = __float_as_uint(Ql_s[r * 36 + k + lr]);
                al[mt][1] = __float_as_uint(Ql_s[(r + 8) * 36 + k + lr]);
                al[mt][2] = __float_as_uint(Ql_s[r * 36 + k + 4 + lr]);
                al[mt][3] = __float_as_uint(Ql_s[(r + 8) * 36 + k + 4 + lr]);
            }
            #pragma unroll
            for (int nt = 0; nt < 4; nt++) {
                const int n = n0 + nt * 8 + lq;
                uint32_t bhf[2], blf[2];
                bhf[0] = __float_as_uint(Ph_s[n * 33 + k + lr]);
                bhf[1] = __float_as_uint(Ph_s[n * 33 + k + 4 + lr]);
                blf[0] = __float_as_uint(Pl_s[n * 33 + k + lr]);
                blf[1] = __float_as_uint(Pl_s[n * 33 + k + 4 + lr]);
                MMA_TF32(acc[0][nt], ah[0], bhf);
                MMA_TF32(acc[1][nt], ah[1], bhf);
                MMA_TF32(acc[0][nt], ah[0], blf);
                MMA_TF32(acc[1][nt], ah[1], blf);
                MMA_TF32(acc[0][nt], al[0], bhf);
                MMA_TF32(acc[1][nt], al[1], bhf);
            }
        }
    }

    float* op = out + base;
    #pragma unroll
    for (int mt = 0; mt < 2; mt++) {
        const int rm = m0 + mt * 16 + lq;
        #pragma unroll
        for (int nt = 0; nt < 4; nt++) {
            const int cn = s0 + n0 + nt * 8 + 2 * lr;
            *reinterpret_cast<float2*>(&op[(size_t)rm * DD + cn]) =
                make_float2(acc[mt][nt][0], acc[mt][nt][1]);
            *reinterpret_cast<float2*>(&op[(size_t)(rm + 8) * DD + cn]) =
                make_float2(acc[mt][nt][2], acc[mt][nt][3]);
        }
    }
}

// ---------------------------------------------------------------------------
extern "C" void kernel_launch(void* const* d_in, const int* in_sizes, int n_in,
                              void* d_out, int out_size)
{
    const float* x    = (const float*)d_in[0];
    const float* Wq   = (const float*)d_in[1];
    const float* bq   = (const float*)d_in[2];
    const float* Wk   = (const float*)d_in[3];
    const float* bk   = (const float*)d_in[4];
    const float* Wv   = (const float*)d_in[5];
    const float* bv   = (const float*)d_in[6];
    const float* temp = (const float*)d_in[7];
    float* out = (float*)d_out;

    static float* Qp = nullptr;
    static float *Kp, *Vp, *Xhi, *Xlo, *Wthi, *Wtlo;
    if (!Qp) {
        cudaGetSymbolAddress((void**)&Qp, g_Q);
        cudaGetSymbolAddress((void**)&Kp, g_K);
        cudaGetSymbolAddress((void**)&Vp, g_V);
        cudaGetSymbolAddress((void**)&Xhi, g_Xhi);
        cudaGetSymbolAddress((void**)&Xlo, g_Xlo);
        cudaGetSymbolAddress((void**)&Wthi, g_Wthi);
        cudaGetSymbolAddress((void**)&Wtlo, g_Wtlo);
        cudaFuncSetAttribute(proj_mma_kernel,
                             cudaFuncAttributeMaxDynamicSharedMemorySize, PROJ_SMEM);
        cudaFuncSetAttribute(attn_mma_kernel,
                             cudaFuncAttributeMaxDynamicSharedMemorySize, ATTN_SMEM);
        cudaFuncSetAttribute(out_mma_kernel,
                             cudaFuncAttributeMaxDynamicSharedMemorySize, OUT_SMEM);
    }

    split_x_kernel<<<BT * DD / 1024, 256>>>(x);
    {
        dim3 tg(32, 32);
        dim3 tb(32, 8);
        wtrans_kernel<<<tg, tb>>>(Wq, 0);
        wtrans_kernel<<<tg, tb>>>(Wk, 1);
        wtrans_kernel<<<tg, tb>>>(Wv, 2);
    }

    dim3 pgrid(DD / 128, BT / 128);   // 8 x 32
    proj_mma_kernel<<<pgrid, 256, PROJ_SMEM>>>(Xhi, Xlo, Wthi + 0 * (size_t)DD * DD, Wtlo + 0 * (size_t)DD * DD, bq, Qp);
    proj_mma_kernel<<<pgrid, 256, PROJ_SMEM>>>(Xhi, Xlo, Wthi + 1 * (size_t)DD * DD, Wtlo + 1 * (size_t)DD * DD, bk, Kp);
    proj_mma_kernel<<<pgrid, 256, PROJ_SMEM>>>(Xhi, Xlo, Wthi + 2 * (size_t)DD * DD, Wtlo + 2 * (size_t)DD * DD, bv, Vp);

    dim3 agrid(TT / 128, TT / 128, BB * HH);  // 8 x 8 x 64
    attn_mma_kernel<<<agrid, 256, ATTN_SMEM>>>(temp);

    rowstat_kernel<<<(BB * HH * TT) / 8, 256>>>();

    dim3 ogrid(TT / 128, 1, BB * HH);         // 8 x 1 x 64
    out_mma_kernel<<<ogrid, 256, OUT_SMEM>>>(out);
}

// round 11
// speedup vs baseline: 1.1650x; 1.1650x over previous
#include <cuda_runtime.h>
#include <cstdint>

// Problem constants
#define BB 4
#define TT 1024
#define DD 1024
#define HH 16
#define DH 64
#define BT (BB*TT)   // 4096

// Scratch (allocation-free: __device__ globals)
__device__ float g_Q[BT*DD];                    // 16 MB
__device__ float g_K[BT*DD];                    // 16 MB
__device__ float g_V[BT*DD];                    // 16 MB
__device__ float g_A[(size_t)BB*HH*TT*TT];      // 256 MB attn matrix
__device__ float g_Xhi[BT*DD];
__device__ float g_Xlo[BT*DD];
__device__ float g_Wthi[3][DD*DD];
__device__ float g_Wtlo[3][DD*DD];
__device__ float g_mx[BB*HH*TT];                // per-row max
__device__ float g_invs[BB*HH*TT];              // per-row 1/sum(exp)
__device__ float g_pmax[BB*HH*TT*8];            // per-(row, s-tile) max
__device__ float g_psum[BB*HH*TT*8];            // per-(row, s-tile) sumexp

// ---------------------------------------------------------------------------
// Helpers
// ---------------------------------------------------------------------------
__device__ __forceinline__ uint32_t smem_u32(const void* p) {
    uint32_t a;
    asm("{ .reg .u64 t; cvta.to.shared.u64 t, %1; cvt.u32.u64 %0, t; }" : "=r"(a) : "l"(p));
    return a;
}
__device__ __forceinline__ float to_tf32(float v) {
    uint32_t u;
    asm("cvt.rna.tf32.f32 %0, %1;" : "=r"(u) : "f"(v));
    return __uint_as_float(u);
}
__device__ __forceinline__ void cp16(uint32_t dst, const void* src) {
    asm volatile("cp.async.cg.shared.global [%0], [%1], 16;" :: "r"(dst), "l"(src));
}
#define CP_COMMIT() asm volatile("cp.async.commit_group;" ::: "memory")
#define CP_WAIT1()  asm volatile("cp.async.wait_group 1;" ::: "memory")
#define CP_WAIT0()  asm volatile("cp.async.wait_group 0;" ::: "memory")

#define MMA_TF32(d, a, b) \
    asm volatile("mma.sync.aligned.m16n8k8.row.col.f32.tf32.tf32.f32 " \
        "{%0,%1,%2,%3}, {%4,%5,%6,%7}, {%8,%9}, {%0,%1,%2,%3};" \
        : "+f"((d)[0]), "+f"((d)[1]), "+f"((d)[2]), "+f"((d)[3]) \
        : "r"((a)[0]), "r"((a)[1]), "r"((a)[2]), "r"((a)[3]), \
          "r"((b)[0]), "r"((b)[1]))

// ---------------------------------------------------------------------------
// Packed f32x2 helpers (FFMA2)
// ---------------------------------------------------------------------------
__device__ __forceinline__ unsigned long long pack2(float lo, float hi) {
    unsigned long long r;
    asm("mov.b64 %0, {%1, %2};" : "=l"(r) : "f"(lo), "f"(hi));
    return r;
}
__device__ __forceinline__ unsigned long long dup2(float v) {
    unsigned long long r;
    asm("mov.b64 %0, {%1, %1};" : "=l"(r) : "f"(v));
    return r;
}
__device__ __forceinline__ void ffma2(unsigned long long& d,
                                      unsigned long long a,
                                      unsigned long long b) {
    asm("fma.rn.f32x2 %0, %1, %2, %0;" : "+l"(d) : "l"(a), "l"(b));
}
__device__ __forceinline__ float2 unpack2(unsigned long long v) {
    float2 r;
    asm("mov.b64 {%0, %1}, %2;" : "=f"(r.x), "=f"(r.y) : "l"(v));
    return r;
}

// ---------------------------------------------------------------------------
// Prep 1: split X into tf32 hi/lo
// ---------------------------------------------------------------------------
__global__ __launch_bounds__(256) void split_x_kernel(const float* __restrict__ x)
{
    const size_t i4 = ((size_t)blockIdx.x * 256 + threadIdx.x) * 4;
    float4 v = *reinterpret_cast<const float4*>(&x[i4]);
    float4 h, l;
    h.x = to_tf32(v.x); l.x = to_tf32(v.x - h.x);
    h.y = to_tf32(v.y); l.y = to_tf32(v.y - h.y);
    h.z = to_tf32(v.z); l.z = to_tf32(v.z - h.z);
    h.w = to_tf32(v.w); l.w = to_tf32(v.w - h.w);
    *reinterpret_cast<float4*>(&g_Xhi[i4]) = h;
    *reinterpret_cast<float4*>(&g_Xlo[i4]) = l;
}

// ---------------------------------------------------------------------------
// Prep 2: transpose W + tf32 hi/lo split: Wt[n][k] = W[k][n]
// ---------------------------------------------------------------------------
__global__ void wtrans_kernel(const float* __restrict__ W, int widx)
{
    __shared__ float s[32][33];
    const int tx = threadIdx.x;
    const int ty = threadIdx.y;
    const int k0 = blockIdx.x * 32;
    const int n0 = blockIdx.y * 32;

    #pragma unroll
    for (int i = 0; i < 4; i++)
        s[ty + i * 8][tx] = W[(size_t)(k0 + ty + i * 8) * DD + n0 + tx];
    __syncthreads();

    float* hi = g_Wthi[widx];
    float* lo = g_Wtlo[widx];
    #pragma unroll
    for (int i = 0; i < 4; i++) {
        float v = s[tx][ty + i * 8];
        float h = to_tf32(v);
        hi[(size_t)(n0 + ty + i * 8) * DD + k0 + tx] = h;
        lo[(size_t)(n0 + ty + i * 8) * DD + k0 + tx] = to_tf32(v - h);
    }
}

// ---------------------------------------------------------------------------
// Kernel 1: projection GEMM via mma.sync m16n8k8 tf32, 3xTF32 hi/lo split.
// ---------------------------------------------------------------------------
#define ROWPAD 36
#define A_F    (128 * ROWPAD)
#define B_F    (128 * 32)
#define STG_F  (2 * A_F + 2 * B_F)
#define PROJ_SMEM (2 * STG_F * 4)
#define NCHUNK 32

__global__ __launch_bounds__(256, 1) void proj_mma_kernel(
    const float* __restrict__ Ahi_g, const float* __restrict__ Alo_g,
    const float* __restrict__ Bhi_g, const float* __restrict__ Blo_g,
    const float* __restrict__ bias, float* __restrict__ C)
{
    extern __shared__ float sm[];
    const uint32_t sbase = smem_u32(sm);

    const int tid = threadIdx.x;
    const int wid = tid >> 5;
    const int lane = tid & 31;
    const int lq  = lane >> 2;
    const int lr  = lane & 3;

    const int row0 = blockIdx.y * 128;
    const int col0 = blockIdx.x * 128;

    const int m0 = (wid >> 1) * 32;
    const int n0 = (wid & 1) * 64;

    auto load_chunk = [&](int kc, int stage) {
        const int k0 = kc * 32;
        const uint32_t st = sbase + (uint32_t)stage * STG_F * 4;
        #pragma unroll
        for (int i = 0; i < 4; i++) {
            const int c = tid + i * 256;
            const int r = c >> 3;
            const int o = c & 7;
            const uint32_t soA = (uint32_t)(r * ROWPAD * 4 + o * 16);
            const uint32_t soB = (uint32_t)(r * 128 + ((o ^ (r & 7)) * 16));
            const size_t ga = (size_t)(row0 + r) * DD + k0 + o * 4;
            const size_t gb = (size_t)(col0 + r) * DD + k0 + o * 4;
            cp16(st + 0 * A_F * 4 + soA, &Ahi_g[ga]);
            cp16(st + 1 * A_F * 4 + soA, &Alo_g[ga]);
            cp16(st + (2 * A_F + 0 * B_F) * 4 + soB, &Bhi_g[gb]);
            cp16(st + (2 * A_F + 1 * B_F) * 4 + soB, &Blo_g[gb]);
        }
        CP_COMMIT();
    };

    float acc[2][8][4];
    #pragma unroll
    for (int mt = 0; mt < 2; mt++)
        #pragma unroll
        for (int nt = 0; nt < 8; nt++)
            #pragma unroll
            for (int r = 0; r < 4; r++)
                acc[mt][nt][r] = 0.f;

    load_chunk(0, 0);
    load_chunk(1, 1);

    for (int kc = 0; kc < NCHUNK; kc++) {
        if (kc == NCHUNK - 1) { CP_WAIT0(); } else { CP_WAIT1(); }
        __syncthreads();

        const float* st = sm + (kc & 1) * STG_F;
        const float* Ah = st;
        const float* Al = st + A_F;
        const float* Bh = st + 2 * A_F;
        const float* Bl = st + 2 * A_F + B_F;

        #pragma unroll
        for (int s = 0; s < 4; s++) {
            const int k = s * 8;
            uint32_t ahi[2][4], alo[2][4];
            #pragma unroll
            for (int mt = 0; mt < 2; mt++) {
                const int r = m0 + mt * 16 + lq;
                ahi[mt][0] = __float_as_uint(Ah[r * ROWPAD + k + lr]);
                ahi[mt][1] = __float_as_uint(Ah[(r + 8) * ROWPAD + k + lr]);
                ahi[mt][2] = __float_as_uint(Ah[r * ROWPAD + k + 4 + lr]);
                ahi[mt][3] = __float_as_uint(Ah[(r + 8) * ROWPAD + k + 4 + lr]);
                alo[mt][0] = __float_as_uint(Al[r * ROWPAD + k + lr]);
                alo[mt][1] = __float_as_uint(Al[(r + 8) * ROWPAD + k + lr]);
                alo[mt][2] = __float_as_uint(Al[r * ROWPAD + k + 4 + lr]);
                alo[mt][3] = __float_as_uint(Al[(r + 8) * ROWPAD + k + 4 + lr]);
            }
            #pragma unroll
            for (int nt = 0; nt < 8; nt++) {
                const int n = n0 + nt * 8 + lq;
                const int nb = n * 32;
                const int x0 = ((2 * s) ^ (n & 7)) << 2;
                const int x1 = ((2 * s + 1) ^ (n & 7)) << 2;
                uint32_t bhi[2], blo[2];
                bhi[0] = __float_as_uint(Bh[nb + x0 + lr]);
                bhi[1] = __float_as_uint(Bh[nb + x1 + lr]);
                blo[0] = __float_as_uint(Bl[nb + x0 + lr]);
                blo[1] = __float_as_uint(Bl[nb + x1 + lr]);
                MMA_TF32(acc[0][nt], ahi[0], bhi);
                MMA_TF32(acc[1][nt], ahi[1], bhi);
                MMA_TF32(acc[0][nt], ahi[0], blo);
                MMA_TF32(acc[1][nt], ahi[1], blo);
                MMA_TF32(acc[0][nt], alo[0], bhi);
                MMA_TF32(acc[1][nt], alo[1], bhi);
            }
        }
        __syncthreads();
        if (kc + 2 < NCHUNK) load_chunk(kc + 2, kc & 1);
    }

    #pragma unroll
    for (int mt = 0; mt < 2; mt++) {
        const int rm = row0 + m0 + mt * 16 + lq;
        #pragma unroll
        for (int nt = 0; nt < 8; nt++) {
            const int cn = col0 + n0 + nt * 8 + 2 * lr;
            const float2 bv = *reinterpret_cast<const float2*>(&bias[cn]);
            float2 v0 = make_float2(acc[mt][nt][0] + bv.x, acc[mt][nt][1] + bv.y);
            float2 v1 = make_float2(acc[mt][nt][2] + bv.x, acc[mt][nt][3] + bv.y);
            *reinterpret_cast<float2*>(&C[(size_t)rm * DD + cn])       = v0;
            *reinterpret_cast<float2*>(&C[(size_t)(rm + 8) * DD + cn]) = v1;
        }
    }
}

// ---------------------------------------------------------------------------
// Kernel 2: attn[b,h,t,s] = temp[h] * sum_d Kh[d,t] * Vh[d,s]   (FFMA2)
// Epilogue additionally emits per-(row, s-tile) partial softmax stats
// (tile max + sumexp) so the 256MB rowstat re-read is eliminated.
// ---------------------------------------------------------------------------
__global__ __launch_bounds__(256) void attn_kernel(const float* __restrict__ temperature)
{
    extern __shared__ float smf[];
    float (*Ks)[128] = reinterpret_cast<float (*)[128]>(smf);
    float (*Vs)[128] = reinterpret_cast<float (*)[128]>(smf + 64*128);

    const int tid = threadIdx.x;
    const int tx = tid & 15;
    const int ty = tid >> 4;
    const int bh = blockIdx.z;
    const int b  = bh >> 4;
    const int h  = bh & 15;
    const int t0 = blockIdx.y * 128;
    const int s0 = blockIdx.x * 128;

    const float* Kh = g_K + (size_t)b * TT * DD + (size_t)(h * DH) * DD;
    const float* Vh = g_V + (size_t)b * TT * DD + (size_t)(h * DH) * DD;

    #pragma unroll
    for (int i = 0; i < 8; i++) {
        const int idx = i * 256 + tid;
        const int d  = idx >> 5;
        const int c4 = (idx & 31) * 4;
        *reinterpret_cast<float4*>(&Ks[d][c4]) =
            *reinterpret_cast<const float4*>(&Kh[(size_t)d * DD + t0 + c4]);
        *reinterpret_cast<float4*>(&Vs[d][c4]) =
            *reinterpret_cast<const float4*>(&Vh[(size_t)d * DD + s0 + c4]);
    }
    __syncthreads();

    unsigned long long acc[4][8] = {};

    #pragma unroll 8
    for (int d = 0; d < 64; d++) {
        float4 a0 = *reinterpret_cast<const float4*>(&Ks[d][ty * 8]);
        float4 a1 = *reinterpret_cast<const float4*>(&Ks[d][ty * 8 + 4]);
        float4 b0 = *reinterpret_cast<const float4*>(&Vs[d][tx * 8]);
        float4 b1 = *reinterpret_cast<const float4*>(&Vs[d][tx * 8 + 4]);
        unsigned long long a2[4] = {pack2(a0.x, a0.y), pack2(a0.z, a0.w),
                                    pack2(a1.x, a1.y), pack2(a1.z, a1.w)};
        unsigned long long bb[8] = {dup2(b0.x), dup2(b0.y), dup2(b0.z), dup2(b0.w),
                                    dup2(b1.x), dup2(b1.y), dup2(b1.z), dup2(b1.w)};
        #pragma unroll
        for (int ip = 0; ip < 4; ip++)
            #pragma unroll
            for (int j = 0; j < 8; j++)
                ffma2(acc[ip][j], a2[ip], bb[j]);
    }

    const float tmp = temperature[h];
    float* Abase = g_A + ((size_t)bh * TT + t0) * TT + s0;
    #pragma unroll
    for (int ip = 0; ip < 4; ip++) {
        float r0[8], r1[8];
        #pragma unroll
        for (int j = 0; j < 8; j++) {
            float2 v = unpack2(acc[ip][j]);
            r0[j] = v.x * tmp;
            r1[j] = v.y * tmp;
        }
        float* p0 = &Abase[(size_t)(ty * 8 + 2 * ip) * TT + tx * 8];
        float* p1 = p0 + TT;
        *reinterpret_cast<float4*>(p0)     = make_float4(r0[0], r0[1], r0[2], r0[3]);
        *reinterpret_cast<float4*>(p0 + 4) = make_float4(r0[4], r0[5], r0[6], r0[7]);
        *reinterpret_cast<float4*>(p1)     = make_float4(r1[0], r1[1], r1[2], r1[3]);
        *reinterpret_cast<float4*>(p1 + 4) = make_float4(r1[4], r1[5], r1[6], r1[7]);

        // partial softmax stats for the two rows (over this 128-col s-tile)
        #pragma unroll
        for (int half = 0; half < 2; half++) {
            const float* rv = half ? r1 : r0;
            float tmax = fmaxf(fmaxf(fmaxf(rv[0], rv[1]), fmaxf(rv[2], rv[3])),
                               fmaxf(fmaxf(rv[4], rv[5]), fmaxf(rv[6], rv[7])));
            #pragma unroll
            for (int off = 8; off > 0; off >>= 1)
                tmax = fmaxf(tmax, __shfl_xor_sync(0xffffffffu, tmax, off));
            float ps = 0.f;
            #pragma unroll
            for (int j = 0; j < 8; j++) ps += __expf(rv[j] - tmax);
            #pragma unroll
            for (int off = 8; off > 0; off >>= 1)
                ps += __shfl_xor_sync(0xffffffffu, ps, off);
            if (tx == 0) {
                const size_t row = (size_t)bh * TT + t0 + ty * 8 + 2 * ip + half;
                g_pmax[row * 8 + blockIdx.x] = tmax;
                g_psum[row * 8 + blockIdx.x] = ps;
            }
        }
    }
}

// ---------------------------------------------------------------------------
// Kernel 3: combine per-tile partial stats into g_mx / g_invs.
// One thread per row; 8 partials each.
// ---------------------------------------------------------------------------
__global__ __launch_bounds__(256) void combine_kernel()
{
    const size_t row = (size_t)blockIdx.x * 256 + threadIdx.x;   // 0..65535
    float4 m0 = *reinterpret_cast<const float4*>(&g_pmax[row * 8]);
    float4 m1 = *reinterpret_cast<const float4*>(&g_pmax[row * 8 + 4]);
    float4 s0 = *reinterpret_cast<const float4*>(&g_psum[row * 8]);
    float4 s1 = *reinterpret_cast<const float4*>(&g_psum[row * 8 + 4]);
    float m = fmaxf(fmaxf(fmaxf(m0.x, m0.y), fmaxf(m0.z, m0.w)),
                    fmaxf(fmaxf(m1.x, m1.y), fmaxf(m1.z, m1.w)));
    float s = s0.x * __expf(m0.x - m) + s0.y * __expf(m0.y - m)
            + s0.z * __expf(m0.z - m) + s0.w * __expf(m0.w - m)
            + s1.x * __expf(m1.x - m) + s1.y * __expf(m1.y - m)
            + s1.z * __expf(m1.z - m) + s1.w * __expf(m1.w - m);
    g_mx[row]   = m;
    g_invs[row] = 1.0f / s;
}

// ---------------------------------------------------------------------------
// Kernel 4: out rows = (Qh * invs) @ exp(A - mx) via mma.sync tf32 3x.
// ---------------------------------------------------------------------------
#define QS_F 2304            // 64*36
#define PS_F 4224            // 128*33
#define OUT_SMEM ((2*QS_F + 2*PS_F) * 4)   // 52224 bytes

__global__ __launch_bounds__(256, 1) void out_mma_kernel(float* __restrict__ out)
{
    extern __shared__ float sm2[];
    float* Qh_s = sm2;                 // [64][36] hi
    float* Ql_s = sm2 + QS_F;          // [64][36] lo
    float* Ph_s = sm2 + 2 * QS_F;      // [128 s][33 t] hi
    float* Pl_s = sm2 + 2 * QS_F + PS_F;

    const int tid = threadIdx.x;
    const int wid = tid >> 5;
    const int lane = tid & 31;
    const int lq = lane >> 2, lr = lane & 3;
    const int bh = blockIdx.z, b = bh >> 4, h = bh & 15;
    const int s0 = blockIdx.x * 128;
    const int m0 = (wid >> 2) * 32;    // 0 or 32
    const int n0 = (wid & 3) * 32;     // 0,32,64,96

    const size_t base = (size_t)b * TT * DD + (size_t)(h * DH) * DD;
    const float* Qg   = g_Q + base;
    const float* Ag   = g_A + (size_t)bh * TT * TT;
    const float* mxp  = g_mx + (size_t)bh * TT;
    const float* invp = g_invs + (size_t)bh * TT;

    const int qr0 = tid >> 3;            // 0..31
    const int qo  = (tid & 7) * 4;       // 0..28

    float acc[2][4][4];
    #pragma unroll
    for (int mt = 0; mt < 2; mt++)
        #pragma unroll
        for (int nt = 0; nt < 4; nt++)
            #pragma unroll
            for (int r = 0; r < 4; r++)
                acc[mt][nt][r] = 0.f;

    float4 qv[2], av[4], iv4;
    float mval[4];

    auto ldg_chunk = [&](int kc) {
        const int k0 = kc * 32;
        iv4 = *reinterpret_cast<const float4*>(&invp[k0 + qo]);
        #pragma unroll
        for (int i = 0; i < 2; i++) {
            const int qr = qr0 + i * 32;
            qv[i] = *reinterpret_cast<const float4*>(&Qg[(size_t)qr * DD + k0 + qo]);
        }
        #pragma unroll
        for (int i = 0; i < 4; i++) {
            const int f = i * 256 + tid;
            const int ar = f >> 5;
            const int ac4 = (f & 31) * 4;
            av[i] = *reinterpret_cast<const float4*>(&Ag[(size_t)(k0 + ar) * TT + s0 + ac4]);
            mval[i] = mxp[k0 + ar];
        }
    };

    ldg_chunk(0);
    for (int kc = 0; kc < 32; kc++) {
        if (kc) __syncthreads();
        #pragma unroll
        for (int i = 0; i < 2; i++) {
            const int qr = qr0 + i * 32;
            float v0 = qv[i].x * iv4.x, v1 = qv[i].y * iv4.y;
            float v2 = qv[i].z * iv4.z, v3 = qv[i].w * iv4.w;
            float h0 = to_tf32(v0), h1 = to_tf32(v1), h2 = to_tf32(v2), h3 = to_tf32(v3);
            *reinterpret_cast<float4*>(&Qh_s[qr * 36 + qo]) = make_float4(h0, h1, h2, h3);
            *reinterpret_cast<float4*>(&Ql_s[qr * 36 + qo]) =
                make_float4(to_tf32(v0 - h0), to_tf32(v1 - h1), to_tf32(v2 - h2), to_tf32(v3 - h3));
        }
        #pragma unroll
        for (int i = 0; i < 4; i++) {
            const int f = i * 256 + tid;
            const int ar = f >> 5;
            const int ac4 = (f & 31) * 4;
            const float m = mval[i];
            float e0 = __expf(av[i].x - m), e1 = __expf(av[i].y - m);
            float e2 = __expf(av[i].z - m), e3 = __expf(av[i].w - m);
            float h0 = to_tf32(e0), h1 = to_tf32(e1), h2 = to_tf32(e2), h3 = to_tf32(e3);
            Ph_s[(ac4 + 0) * 33 + ar] = h0;
            Ph_s[(ac4 + 1) * 33 + ar] = h1;
            Ph_s[(ac4 + 2) * 33 + ar] = h2;
            Ph_s[(ac4 + 3) * 33 + ar] = h3;
            Pl_s[(ac4 + 0) * 33 + ar] = to_tf32(e0 - h0);
            Pl_s[(ac4 + 1) * 33 + ar] = to_tf32(e1 - h1);
            Pl_s[(ac4 + 2) * 33 + ar] = to_tf32(e2 - h2);
            Pl_s[(ac4 + 3) * 33 + ar] = to_tf32(e3 - h3);
        }
        __syncthreads();
        if (kc + 1 < 32) ldg_chunk(kc + 1);

        #pragma unroll
        for (int s = 0; s < 4; s++) {
            const int k = s * 8;
            uint32_t ah[2][4], al[2][4];
            #pragma unroll
            for (int mt = 0; mt < 2; mt++) {
                const int r = m0 + mt * 16 + lq;
                ah[mt][0] = __float_as_uint(Qh_s[r * 36 + k + lr]);
                ah[mt][1] = __float_as_uint(Qh_s[(r + 8) * 36 + k + lr]);
                ah[mt][2] = __float_as_uint(Qh_s[r * 36 + k + 4 + lr]);
                ah[mt][3] = __float_as_uint(Qh_s[(r + 8) * 36 + k + 4 + lr]);
                al[mt][0] = __float_as_uint(Ql_s[r * 36 + k + lr]);
                al[mt][1] = __float_as_uint(Ql_s[(r + 8) * 36 + k + lr]);
                al[mt][2] = __float_as_uint(Ql_s[r * 36 + k + 4 + lr]);
                al[mt][3] = __float_as_uint(Ql_s[(r + 8) * 36 + k + 4 + lr]);
            }
            #pragma unroll
            for (int nt = 0; nt < 4; nt++) {
                const int n = n0 + nt * 8 + lq;
                uint32_t bhf[2], blf[2];
                bhf[0] = __float_as_uint(Ph_s[n * 33 + k + lr]);
                bhf[1] = __float_as_uint(Ph_s[n * 33 + k + 4 + lr]);
                blf[0] = __float_as_uint(Pl_s[n * 33 + k + lr]);
                blf[1] = __float_as_uint(Pl_s[n * 33 + k + 4 + lr]);
                MMA_TF32(acc[0][nt], ah[0], bhf);
                MMA_TF32(acc[1][nt], ah[1], bhf);
                MMA_TF32(acc[0][nt], ah[0], blf);
                MMA_TF32(acc[1][nt], ah[1], blf);
                MMA_TF32(acc[0][nt], al[0], bhf);
                MMA_TF32(acc[1][nt], al[1], bhf);
            }
        }
    }

    float* op = out + base;
    #pragma unroll
    for (int mt = 0; mt < 2; mt++) {
        const int rm = m0 + mt * 16 + lq;
        #pragma unroll
        for (int nt = 0; nt < 4; nt++) {
            const int cn = s0 + n0 + nt * 8 + 2 * lr;
            *reinterpret_cast<float2*>(&op[(size_t)rm * DD + cn]) =
                make_float2(acc[mt][nt][0], acc[mt][nt][1]);
            *reinterpret_cast<float2*>(&op[(size_t)(rm + 8) * DD + cn]) =
                make_float2(acc[mt][nt][2], acc[mt][nt][3]);
        }
    }
}

// ---------------------------------------------------------------------------
extern "C" void kernel_launch(void* const* d_in, const int* in_sizes, int n_in,
                              void* d_out, int out_size)
{
    const float* x    = (const float*)d_in[0];
    const float* Wq   = (const float*)d_in[1];
    const float* bq   = (const float*)d_in[2];
    const float* Wk   = (const float*)d_in[3];
    const float* bk   = (const float*)d_in[4];
    const float* Wv   = (const float*)d_in[5];
    const float* bv   = (const float*)d_in[6];
    const float* temp = (const float*)d_in[7];
    float* out = (float*)d_out;

    static float* Qp = nullptr;
    static float *Kp, *Vp, *Xhi, *Xlo, *Wthi, *Wtlo;
    if (!Qp) {
        cudaGetSymbolAddress((void**)&Qp, g_Q);
        cudaGetSymbolAddress((void**)&Kp, g_K);
        cudaGetSymbolAddress((void**)&Vp, g_V);
        cudaGetSymbolAddress((void**)&Xhi, g_Xhi);
        cudaGetSymbolAddress((void**)&Xlo, g_Xlo);
        cudaGetSymbolAddress((void**)&Wthi, g_Wthi);
        cudaGetSymbolAddress((void**)&Wtlo, g_Wtlo);
        cudaFuncSetAttribute(proj_mma_kernel,
                             cudaFuncAttributeMaxDynamicSharedMemorySize, PROJ_SMEM);
        cudaFuncSetAttribute(attn_kernel,
                             cudaFuncAttributeMaxDynamicSharedMemorySize, 65536);
        cudaFuncSetAttribute(out_mma_kernel,
                             cudaFuncAttributeMaxDynamicSharedMemorySize, OUT_SMEM);
    }

    split_x_kernel<<<BT * DD / 1024, 256>>>(x);
    {
        dim3 tg(32, 32);
        dim3 tb(32, 8);
        wtrans_kernel<<<tg, tb>>>(Wq, 0);
        wtrans_kernel<<<tg, tb>>>(Wk, 1);
        wtrans_kernel<<<tg, tb>>>(Wv, 2);
    }

    dim3 pgrid(DD / 128, BT / 128);   // 8 x 32
    proj_mma_kernel<<<pgrid, 256, PROJ_SMEM>>>(Xhi, Xlo, Wthi + 0 * (size_t)DD * DD, Wtlo + 0 * (size_t)DD * DD, bq, Qp);
    proj_mma_kernel<<<pgrid, 256, PROJ_SMEM>>>(Xhi, Xlo, Wthi + 1 * (size_t)DD * DD, Wtlo + 1 * (size_t)DD * DD, bk, Kp);
    proj_mma_kernel<<<pgrid, 256, PROJ_SMEM>>>(Xhi, Xlo, Wthi + 2 * (size_t)DD * DD, Wtlo + 2 * (size_t)DD * DD, bv, Vp);

    dim3 agrid(TT / 128, TT / 128, BB * HH);  // 8 x 8 x 64
    attn_kernel<<<agrid, 256, 65536>>>(temp);

    combine_kernel<<<(BB * HH * TT) / 256, 256>>>();

    dim3 ogrid(TT / 128, 1, BB * HH);         // 8 x 1 x 64
    out_mma_kernel<<<ogrid, 256, OUT_SMEM>>>(out);
}